// round 5
// baseline (speedup 1.0000x reference)
#include <cuda_runtime.h>
#include <cuda_fp16.h>
#include <math.h>

#define N_NODES 100000
#define N_EDGES 1600000
#define D_IN 64
#define D_OUT 64
#define D_EDGE 16
#define NBLK_SCAN ((N_NODES + 255) / 256)   // 391

#define FMA_F32X2(d, a, b, c) \
    asm("fma.rn.f32x2 %0, %1, %2, %3;" : "=l"(d) : "l"(a), "l"(b), "l"(c))

// ---------------- scratch (device globals; no allocation) ----------------
__device__ float g_u[80];                         // W1^T @ att_l
__device__ float g_al[N_NODES];                   // x . u[0:64]
__device__ float g_ar[N_NODES];                   // x . att_r
__device__ __half2 g_xh[N_NODES * 32];            // x rows in half2 (lane l -> dims 2l,2l+1)
__device__ float g_A[N_NODES * 64];               // aggregated sum ex*x[src]
__device__ float g_den[N_NODES];                  // sum of ex
__device__ int   g_cnt[N_NODES];
__device__ int   g_off[N_NODES];
__device__ int   g_cursor[N_NODES];
__device__ int   g_bsum[NBLK_SCAN];
__device__ int   g_bscan[NBLK_SCAN];
__device__ unsigned long long g_cedge[N_EDGES];   // packed (ex<<32 | src)

// ---------------- K1: u[c] = sum_o att_l[o] * W1[o][c] ----------------
__global__ void k_u(const float* __restrict__ W1, const float* __restrict__ att_l) {
    int c = threadIdx.x;
    if (c < 80) {
        float acc = 0.0f;
        #pragma unroll
        for (int o = 0; o < D_OUT; o++) acc += att_l[o] * W1[o * 80 + c];
        g_u[c] = acc;
    }
}

// ---------------- K2: warp-per-node al/ar + half2 conversion + zero cnt ----------------
__global__ void k_pre(const float* __restrict__ x, const float* __restrict__ att_r) {
    int n = (blockIdx.x * blockDim.x + threadIdx.x) >> 5;
    if (n >= N_NODES) return;
    int lane = threadIdx.x & 31;

    float2 v = __ldg(reinterpret_cast<const float2*>(x) + n * 32 + lane);
    g_xh[n * 32 + lane] = __floats2half2_rn(v.x, v.y);

    float pa = v.x * g_u[2 * lane] + v.y * g_u[2 * lane + 1];
    float pr = v.x * att_r[2 * lane] + v.y * att_r[2 * lane + 1];
    #pragma unroll
    for (int off = 16; off; off >>= 1) {
        pa += __shfl_xor_sync(0xFFFFFFFFu, pa, off);
        pr += __shfl_xor_sync(0xFFFFFFFFu, pr, off);
    }
    if (lane == 0) {
        g_al[n] = pa;
        g_ar[n] = pr;
        g_cnt[n] = 0;
    }
}

// ---------------- K3: histogram of dst ----------------
__global__ void k_count(const int* __restrict__ dst) {
    int e = blockIdx.x * blockDim.x + threadIdx.x;
    if (e < N_EDGES) atomicAdd(&g_cnt[dst[e]], 1);
}

// ---------------- K4a/b/c: exclusive scan ----------------
__global__ void k_scan_a() {
    int tid = threadIdx.x, lane = tid & 31, wid = tid >> 5;
    int i = blockIdx.x * 256 + tid;
    int v = (i < N_NODES) ? g_cnt[i] : 0;
    int inc = v;
    #pragma unroll
    for (int d = 1; d < 32; d <<= 1) {
        int t = __shfl_up_sync(0xFFFFFFFFu, inc, d);
        if (lane >= d) inc += t;
    }
    __shared__ int wsum[8];
    if (lane == 31) wsum[wid] = inc;
    __syncthreads();
    if (tid < 8) {
        int w = wsum[tid];
        #pragma unroll
        for (int d = 1; d < 8; d <<= 1) {
            int t = __shfl_up_sync(0xFFu, w, d);
            if (tid >= d) w += t;
        }
        wsum[tid] = w;
    }
    __syncthreads();
    int base = (wid > 0) ? wsum[wid - 1] : 0;
    if (i < N_NODES) g_off[i] = base + inc - v;
    if (tid == 0) g_bsum[blockIdx.x] = wsum[7];
}

__global__ void k_scan_b() {
    int tid = threadIdx.x, lane = tid & 31, wid = tid >> 5;
    int v = (tid < NBLK_SCAN) ? g_bsum[tid] : 0;
    int inc = v;
    #pragma unroll
    for (int d = 1; d < 32; d <<= 1) {
        int t = __shfl_up_sync(0xFFFFFFFFu, inc, d);
        if (lane >= d) inc += t;
    }
    __shared__ int wsum[16];
    if (lane == 31) wsum[wid] = inc;
    __syncthreads();
    if (tid < 16) {
        int w = wsum[tid];
        #pragma unroll
        for (int d = 1; d < 16; d <<= 1) {
            int t = __shfl_up_sync(0xFFFFu, w, d);
            if (tid >= d) w += t;
        }
        wsum[tid] = w;
    }
    __syncthreads();
    int base = (wid > 0) ? wsum[wid - 1] : 0;
    if (tid < NBLK_SCAN) g_bscan[tid] = base + inc - v;
}

__global__ void k_scan_c() {
    int i = blockIdx.x * blockDim.x + threadIdx.x;
    if (i < N_NODES) {
        int o = g_off[i] + g_bscan[i >> 8];
        g_off[i] = o;
        g_cursor[i] = o;
    }
}

// ---------------- K5: fused edge score + direct CSR scatter ----------------
__global__ void k_edge(const float* __restrict__ edge_attr,
                       const int* __restrict__ src, const int* __restrict__ dst) {
    __shared__ float su[16];
    if (threadIdx.x < 16) su[threadIdx.x] = g_u[64 + threadIdx.x];
    __syncthreads();

    int e = blockIdx.x * blockDim.x + threadIdx.x;
    if (e >= N_EDGES) return;

    const float4* ea = reinterpret_cast<const float4*>(edge_attr) + e * 4;
    float p = 0.0f;
    #pragma unroll
    for (int q = 0; q < 4; q++) {
        float4 v = __ldg(&ea[q]);
        p += v.x * su[q * 4 + 0] + v.y * su[q * 4 + 1]
           + v.z * su[q * 4 + 2] + v.w * su[q * 4 + 3];
    }
    int s = src[e], d = dst[e];
    float ee = g_al[s] + g_ar[d] + p;
    ee = (ee > 0.0f) ? ee : 0.01f * ee;
    float ex = __expf(ee);

    int pos = atomicAdd(&g_cursor[d], 1);
    g_cedge[pos] =
        ((unsigned long long)__float_as_uint(ex) << 32) | (unsigned)s;
}

// ---------------- K6: warp-per-dst aggregation ONLY -> g_A, g_den ----------------
__global__ void k_agg() {
    int lane = threadIdx.x & 31, wid = threadIdx.x >> 5;

    for (int n = blockIdx.x * 8 + wid; n < N_NODES; n += gridDim.x * 8) {
        int start = g_off[n];
        int cnt = g_cnt[n];
        float ax = 0.0f, ay = 0.0f, den = 0.0f;   // lane holds dims (2*lane, 2*lane+1)

        int i = 0;
        for (; i + 4 <= cnt; i += 4) {
            unsigned long long p0 = g_cedge[start + i + 0];
            unsigned long long p1 = g_cedge[start + i + 1];
            unsigned long long p2 = g_cedge[start + i + 2];
            unsigned long long p3 = g_cedge[start + i + 3];
            int s0 = (int)(p0 & 0xFFFFFFFFu), s1 = (int)(p1 & 0xFFFFFFFFu);
            int s2 = (int)(p2 & 0xFFFFFFFFu), s3 = (int)(p3 & 0xFFFFFFFFu);
            float e0 = __uint_as_float((unsigned)(p0 >> 32));
            float e1 = __uint_as_float((unsigned)(p1 >> 32));
            float e2 = __uint_as_float((unsigned)(p2 >> 32));
            float e3 = __uint_as_float((unsigned)(p3 >> 32));
            float2 v0 = __half22float2(__ldg(&g_xh[s0 * 32 + lane]));
            float2 v1 = __half22float2(__ldg(&g_xh[s1 * 32 + lane]));
            float2 v2 = __half22float2(__ldg(&g_xh[s2 * 32 + lane]));
            float2 v3 = __half22float2(__ldg(&g_xh[s3 * 32 + lane]));
            den += (e0 + e1) + (e2 + e3);
            ax += e0 * v0.x + e1 * v1.x + e2 * v2.x + e3 * v3.x;
            ay += e0 * v0.y + e1 * v1.y + e2 * v2.y + e3 * v3.y;
        }
        for (; i < cnt; i++) {
            unsigned long long p0 = g_cedge[start + i];
            int s0 = (int)(p0 & 0xFFFFFFFFu);
            float e0 = __uint_as_float((unsigned)(p0 >> 32));
            float2 v0 = __half22float2(__ldg(&g_xh[s0 * 32 + lane]));
            den += e0;
            ax += e0 * v0.x;
            ay += e0 * v0.y;
        }

        reinterpret_cast<float2*>(g_A)[n * 32 + lane] = make_float2(ax, ay);
        if (lane == 0) g_den[n] = den;
    }
}

// ---------------- K7: node-per-thread tiled GEMM (f32x2) + bias + LayerNorm ----------------
__global__ void __launch_bounds__(128) k_out(
        const float* __restrict__ W2, const float* __restrict__ bias,
        const float* __restrict__ gamma, const float* __restrict__ beta,
        float* __restrict__ out) {
    __shared__ __align__(16) float a_s[64 * 128];   // a_s[k*128 + t] (transposed A tile)
    __shared__ __align__(16) float w2s[64 * 64];    // w2s[k*64 + j] = W2[j][k]
    int tid = threadIdx.x;
    int node0 = blockIdx.x * 128;

    for (int i = tid; i < 64 * 64; i += 128) {
        int j = i >> 6, k = i & 63;
        w2s[k * 64 + j] = W2[i];
    }
    for (int idx = tid; idx < 128 * 16; idx += 128) {
        int node = idx >> 4, k4 = idx & 15;
        int n = node0 + node;
        float4 v = (n < N_NODES)
            ? __ldg(reinterpret_cast<const float4*>(g_A) + n * 16 + k4)
            : make_float4(0.f, 0.f, 0.f, 0.f);
        a_s[(k4 * 4 + 0) * 128 + node] = v.x;
        a_s[(k4 * 4 + 1) * 128 + node] = v.y;
        a_s[(k4 * 4 + 2) * 128 + node] = v.z;
        a_s[(k4 * 4 + 3) * 128 + node] = v.w;
    }
    __syncthreads();

    int n = node0 + tid;
    float den = (n < N_NODES) ? g_den[n] : 1.0f;
    float inv = (den > 0.0f) ? (1.0f / den) : 0.0f;

    unsigned long long acc[32];
    #pragma unroll
    for (int jp = 0; jp < 32; jp++) acc[jp] = 0ull;

    #pragma unroll 4
    for (int k = 0; k < 64; k++) {
        float a = a_s[k * 128 + tid];
        unsigned long long aa;
        asm("mov.b64 %0, {%1, %1};" : "=l"(aa) : "f"(a));
        const unsigned long long* wrow =
            reinterpret_cast<const unsigned long long*>(w2s + k * 64);
        #pragma unroll
        for (int jp = 0; jp < 32; jp++) {
            unsigned long long w = wrow[jp];     // LDS.64 broadcast
            FMA_F32X2(acc[jp], aa, w, acc[jp]);
        }
    }

    // unpack, normalize, bias
    float h[64];
    #pragma unroll
    for (int jp = 0; jp < 32; jp++) {
        float lo, hi;
        asm("mov.b64 {%0, %1}, %2;" : "=f"(lo), "=f"(hi) : "l"(acc[jp]));
        h[2 * jp]     = lo * inv + __ldg(&bias[2 * jp]);
        h[2 * jp + 1] = hi * inv + __ldg(&bias[2 * jp + 1]);
    }

    float sm = 0.0f;
    #pragma unroll
    for (int j = 0; j < 64; j++) sm += h[j];
    float mu = sm * (1.0f / 64.0f);
    float vs = 0.0f;
    #pragma unroll
    for (int j = 0; j < 64; j++) { float d = h[j] - mu; vs += d * d; }
    float rstd = rsqrtf(vs * (1.0f / 64.0f) + 1e-5f);

    __syncthreads();   // done reading a_s; reuse it for output staging
    #pragma unroll
    for (int j = 0; j < 64; j++) {
        a_s[j * 128 + tid] =
            (h[j] - mu) * rstd * __ldg(&gamma[j]) + __ldg(&beta[j]);
    }
    __syncthreads();

    for (int idx = tid; idx < 128 * 16; idx += 128) {
        int node = idx >> 4, k4 = idx & 15;
        int n2 = node0 + node;
        if (n2 < N_NODES) {
            float4 v;
            v.x = a_s[(k4 * 4 + 0) * 128 + node];
            v.y = a_s[(k4 * 4 + 1) * 128 + node];
            v.z = a_s[(k4 * 4 + 2) * 128 + node];
            v.w = a_s[(k4 * 4 + 3) * 128 + node];
            reinterpret_cast<float4*>(out)[n2 * 16 + k4] = v;
        }
    }
}

// ---------------- launch ----------------
extern "C" void kernel_launch(void* const* d_in, const int* in_sizes, int n_in,
                              void* d_out, int out_size) {
    const float* x         = (const float*)d_in[0];
    const float* edge_attr = (const float*)d_in[1];
    const float* W1        = (const float*)d_in[2];
    const float* W2        = (const float*)d_in[3];
    const float* att_l     = (const float*)d_in[4];
    const float* att_r     = (const float*)d_in[5];
    const float* bias      = (const float*)d_in[6];
    const float* ln_gamma  = (const float*)d_in[7];
    const float* ln_beta   = (const float*)d_in[8];
    const int*   src       = (const int*)d_in[9];
    const int*   dst       = (const int*)d_in[10];
    float* out = (float*)d_out;

    k_u<<<1, 96>>>(W1, att_l);
    k_pre<<<(N_NODES * 32 + 255) / 256, 256>>>(x, att_r);
    k_count<<<(N_EDGES + 255) / 256, 256>>>(dst);
    k_scan_a<<<NBLK_SCAN, 256>>>();
    k_scan_b<<<1, 512>>>();
    k_scan_c<<<(N_NODES + 255) / 256, 256>>>();
    k_edge<<<(N_EDGES + 255) / 256, 256>>>(edge_attr, src, dst);
    k_agg<<<2048, 256>>>();
    k_out<<<(N_NODES + 127) / 128, 128>>>(W2, bias, ln_gamma, ln_beta, out);
}

// round 6
// speedup vs baseline: 1.0013x; 1.0013x over previous
#include <cuda_runtime.h>
#include <cuda_fp16.h>
#include <math.h>

#define N_NODES 100000
#define N_EDGES 1600000
#define D_IN 64
#define D_OUT 64
#define D_EDGE 16
#define NBLK_SCAN ((N_NODES + 255) / 256)   // 391

#define FMA_F32X2(d, a, b, c) \
    asm("fma.rn.f32x2 %0, %1, %2, %3;" : "=l"(d) : "l"(a), "l"(b), "l"(c))

// ---------------- scratch (device globals; no allocation) ----------------
__device__ float g_u[80];                         // W1^T @ att_l
__device__ float g_al[N_NODES];                   // x . u[0:64]
__device__ float g_ar[N_NODES];                   // x . att_r
__device__ __half2 g_xh[N_NODES * 32];            // x rows in half2 (lane l -> dims 2l,2l+1)
__device__ float g_A[N_NODES * 64];               // aggregated sum ex*x[src]
__device__ float g_den[N_NODES];                  // sum of ex
__device__ int   g_cnt[N_NODES];
__device__ int   g_off[N_NODES];
__device__ int   g_rank[N_EDGES];                 // edge's arrival order within its dst
__device__ int   g_bsum[NBLK_SCAN];
__device__ unsigned long long g_cedge[N_EDGES];   // packed (ex<<32 | src)

// ---------------- K1: u[c] = sum_o att_l[o] * W1[o][c] ----------------
__global__ void k_u(const float* __restrict__ W1, const float* __restrict__ att_l) {
    int c = threadIdx.x;
    if (c < 80) {
        float acc = 0.0f;
        #pragma unroll
        for (int o = 0; o < D_OUT; o++) acc += att_l[o] * W1[o * 80 + c];
        g_u[c] = acc;
    }
}

// ---------------- K2: warp-per-node al/ar + half2 conversion + zero cnt ----------------
__global__ void k_pre(const float* __restrict__ x, const float* __restrict__ att_r) {
    int n = (blockIdx.x * blockDim.x + threadIdx.x) >> 5;
    if (n >= N_NODES) return;
    int lane = threadIdx.x & 31;

    float2 v = __ldg(reinterpret_cast<const float2*>(x) + n * 32 + lane);
    g_xh[n * 32 + lane] = __floats2half2_rn(v.x, v.y);

    float pa = v.x * g_u[2 * lane] + v.y * g_u[2 * lane + 1];
    float pr = v.x * att_r[2 * lane] + v.y * att_r[2 * lane + 1];
    #pragma unroll
    for (int off = 16; off; off >>= 1) {
        pa += __shfl_xor_sync(0xFFFFFFFFu, pa, off);
        pr += __shfl_xor_sync(0xFFFFFFFFu, pr, off);
    }
    if (lane == 0) {
        g_al[n] = pa;
        g_ar[n] = pr;
        g_cnt[n] = 0;
    }
}

// ---------------- K3: histogram of dst + per-edge rank ----------------
__global__ void k_count(const int* __restrict__ dst) {
    int e = blockIdx.x * blockDim.x + threadIdx.x;
    if (e < N_EDGES) g_rank[e] = atomicAdd(&g_cnt[dst[e]], 1);
}

// ---------------- K4a: per-block exclusive scan ----------------
__global__ void k_scan_a() {
    int tid = threadIdx.x, lane = tid & 31, wid = tid >> 5;
    int i = blockIdx.x * 256 + tid;
    int v = (i < N_NODES) ? g_cnt[i] : 0;
    int inc = v;
    #pragma unroll
    for (int d = 1; d < 32; d <<= 1) {
        int t = __shfl_up_sync(0xFFFFFFFFu, inc, d);
        if (lane >= d) inc += t;
    }
    __shared__ int wsum[8];
    if (lane == 31) wsum[wid] = inc;
    __syncthreads();
    if (tid < 8) {
        int w = wsum[tid];
        #pragma unroll
        for (int d = 1; d < 8; d <<= 1) {
            int t = __shfl_up_sync(0xFFu, w, d);
            if (tid >= d) w += t;
        }
        wsum[tid] = w;
    }
    __syncthreads();
    int base = (wid > 0) ? wsum[wid - 1] : 0;
    if (i < N_NODES) g_off[i] = base + inc - v;
    if (tid == 0) g_bsum[blockIdx.x] = wsum[7];
}

// ---------------- K4b: add cross-block base (each block reduces bsum[0..b)) ----------------
__global__ void k_scan_c() {
    int tid = threadIdx.x;
    int b = blockIdx.x;
    int acc = 0;
    for (int k = tid; k < b; k += 256) acc += g_bsum[k];
    // block reduce
    #pragma unroll
    for (int off = 16; off; off >>= 1) acc += __shfl_xor_sync(0xFFFFFFFFu, acc, off);
    __shared__ int ws[8];
    if ((tid & 31) == 0) ws[tid >> 5] = acc;
    __syncthreads();
    __shared__ int base_s;
    if (tid == 0) {
        int t = 0;
        #pragma unroll
        for (int w = 0; w < 8; w++) t += ws[w];
        base_s = t;
    }
    __syncthreads();
    int i = b * 256 + tid;
    if (i < N_NODES) g_off[i] += base_s;
}

// ---------------- K5: fused edge score + atomic-free CSR scatter ----------------
__global__ void k_edge(const float* __restrict__ edge_attr,
                       const int* __restrict__ src, const int* __restrict__ dst) {
    __shared__ float su[16];
    if (threadIdx.x < 16) su[threadIdx.x] = g_u[64 + threadIdx.x];
    __syncthreads();

    int e = blockIdx.x * blockDim.x + threadIdx.x;
    if (e >= N_EDGES) return;

    const float4* ea = reinterpret_cast<const float4*>(edge_attr) + e * 4;
    float p = 0.0f;
    #pragma unroll
    for (int q = 0; q < 4; q++) {
        float4 v = __ldg(&ea[q]);
        p += v.x * su[q * 4 + 0] + v.y * su[q * 4 + 1]
           + v.z * su[q * 4 + 2] + v.w * su[q * 4 + 3];
    }
    int s = src[e], d = dst[e];
    float ee = g_al[s] + g_ar[d] + p;
    ee = (ee > 0.0f) ? ee : 0.01f * ee;
    float ex = __expf(ee);

    int pos = g_off[d] + g_rank[e];
    g_cedge[pos] =
        ((unsigned long long)__float_as_uint(ex) << 32) | (unsigned)s;
}

// ---------------- K6: warp-per-dst aggregation (lane-parallel packed load,
//                     shfl broadcast, 8-wide gather pipeline) ----------------
__global__ void k_agg() {
    int lane = threadIdx.x & 31, wid = threadIdx.x >> 5;
    int n = blockIdx.x * 8 + wid;
    if (n >= N_NODES) return;

    int start = g_off[n];
    int cnt = g_cnt[n];
    float ax = 0.0f, ay = 0.0f, den = 0.0f;   // lane holds dims (2*lane, 2*lane+1)

    for (int base = 0; base < cnt; base += 32) {
        int m = min(32, cnt - base);
        unsigned long long pk = 0;
        if (lane < m) pk = g_cedge[start + base + lane];   // coalesced chunk load

        int j = 0;
        for (; j + 8 <= m; j += 8) {
            unsigned long long q0 = __shfl_sync(0xFFFFFFFFu, pk, j + 0);
            unsigned long long q1 = __shfl_sync(0xFFFFFFFFu, pk, j + 1);
            unsigned long long q2 = __shfl_sync(0xFFFFFFFFu, pk, j + 2);
            unsigned long long q3 = __shfl_sync(0xFFFFFFFFu, pk, j + 3);
            unsigned long long q4 = __shfl_sync(0xFFFFFFFFu, pk, j + 4);
            unsigned long long q5 = __shfl_sync(0xFFFFFFFFu, pk, j + 5);
            unsigned long long q6 = __shfl_sync(0xFFFFFFFFu, pk, j + 6);
            unsigned long long q7 = __shfl_sync(0xFFFFFFFFu, pk, j + 7);
            float2 v0 = __half22float2(__ldg(&g_xh[(int)(q0 & 0xFFFFFFFFu) * 32 + lane]));
            float2 v1 = __half22float2(__ldg(&g_xh[(int)(q1 & 0xFFFFFFFFu) * 32 + lane]));
            float2 v2 = __half22float2(__ldg(&g_xh[(int)(q2 & 0xFFFFFFFFu) * 32 + lane]));
            float2 v3 = __half22float2(__ldg(&g_xh[(int)(q3 & 0xFFFFFFFFu) * 32 + lane]));
            float2 v4 = __half22float2(__ldg(&g_xh[(int)(q4 & 0xFFFFFFFFu) * 32 + lane]));
            float2 v5 = __half22float2(__ldg(&g_xh[(int)(q5 & 0xFFFFFFFFu) * 32 + lane]));
            float2 v6 = __half22float2(__ldg(&g_xh[(int)(q6 & 0xFFFFFFFFu) * 32 + lane]));
            float2 v7 = __half22float2(__ldg(&g_xh[(int)(q7 & 0xFFFFFFFFu) * 32 + lane]));
            float e0 = __uint_as_float((unsigned)(q0 >> 32));
            float e1 = __uint_as_float((unsigned)(q1 >> 32));
            float e2 = __uint_as_float((unsigned)(q2 >> 32));
            float e3 = __uint_as_float((unsigned)(q3 >> 32));
            float e4 = __uint_as_float((unsigned)(q4 >> 32));
            float e5 = __uint_as_float((unsigned)(q5 >> 32));
            float e6 = __uint_as_float((unsigned)(q6 >> 32));
            float e7 = __uint_as_float((unsigned)(q7 >> 32));
            den += ((e0 + e1) + (e2 + e3)) + ((e4 + e5) + (e6 + e7));
            ax += e0 * v0.x + e1 * v1.x + e2 * v2.x + e3 * v3.x;
            ax += e4 * v4.x + e5 * v5.x + e6 * v6.x + e7 * v7.x;
            ay += e0 * v0.y + e1 * v1.y + e2 * v2.y + e3 * v3.y;
            ay += e4 * v4.y + e5 * v5.y + e6 * v6.y + e7 * v7.y;
        }
        for (; j < m; j++) {
            unsigned long long q0 = __shfl_sync(0xFFFFFFFFu, pk, j);
            float e0 = __uint_as_float((unsigned)(q0 >> 32));
            float2 v0 = __half22float2(__ldg(&g_xh[(int)(q0 & 0xFFFFFFFFu) * 32 + lane]));
            den += e0;
            ax += e0 * v0.x;
            ay += e0 * v0.y;
        }
    }

    reinterpret_cast<float2*>(g_A)[n * 32 + lane] = make_float2(ax, ay);
    if (lane == 0) g_den[n] = den;
}

// ---------------- K7: node-per-thread tiled GEMM (f32x2) + bias + LayerNorm ----------------
__global__ void __launch_bounds__(128) k_out(
        const float* __restrict__ W2, const float* __restrict__ bias,
        const float* __restrict__ gamma, const float* __restrict__ beta,
        float* __restrict__ out) {
    __shared__ __align__(16) float a_s[64 * 128];   // a_s[k*128 + t] (transposed A tile)
    __shared__ __align__(16) float w2s[64 * 64];    // w2s[k*64 + j] = W2[j][k]
    int tid = threadIdx.x;
    int node0 = blockIdx.x * 128;

    for (int i = tid; i < 64 * 64; i += 128) {
        int j = i >> 6, k = i & 63;
        w2s[k * 64 + j] = W2[i];
    }
    for (int idx = tid; idx < 128 * 16; idx += 128) {
        int node = idx >> 4, k4 = idx & 15;
        int n = node0 + node;
        float4 v = (n < N_NODES)
            ? __ldg(reinterpret_cast<const float4*>(g_A) + n * 16 + k4)
            : make_float4(0.f, 0.f, 0.f, 0.f);
        a_s[(k4 * 4 + 0) * 128 + node] = v.x;
        a_s[(k4 * 4 + 1) * 128 + node] = v.y;
        a_s[(k4 * 4 + 2) * 128 + node] = v.z;
        a_s[(k4 * 4 + 3) * 128 + node] = v.w;
    }
    __syncthreads();

    int n = node0 + tid;
    float den = (n < N_NODES) ? g_den[n] : 1.0f;
    float inv = (den > 0.0f) ? (1.0f / den) : 0.0f;

    unsigned long long acc[32];
    #pragma unroll
    for (int jp = 0; jp < 32; jp++) acc[jp] = 0ull;

    #pragma unroll 4
    for (int k = 0; k < 64; k++) {
        float a = a_s[k * 128 + tid];
        unsigned long long aa;
        asm("mov.b64 %0, {%1, %1};" : "=l"(aa) : "f"(a));
        const unsigned long long* wrow =
            reinterpret_cast<const unsigned long long*>(w2s + k * 64);
        #pragma unroll
        for (int jp = 0; jp < 32; jp++) {
            unsigned long long w = wrow[jp];     // LDS.64 broadcast
            FMA_F32X2(acc[jp], aa, w, acc[jp]);
        }
    }

    float h[64];
    #pragma unroll
    for (int jp = 0; jp < 32; jp++) {
        float lo, hi;
        asm("mov.b64 {%0, %1}, %2;" : "=f"(lo), "=f"(hi) : "l"(acc[jp]));
        h[2 * jp]     = lo * inv + __ldg(&bias[2 * jp]);
        h[2 * jp + 1] = hi * inv + __ldg(&bias[2 * jp + 1]);
    }

    float sm = 0.0f;
    #pragma unroll
    for (int j = 0; j < 64; j++) sm += h[j];
    float mu = sm * (1.0f / 64.0f);
    float vs = 0.0f;
    #pragma unroll
    for (int j = 0; j < 64; j++) { float d = h[j] - mu; vs += d * d; }
    float rstd = rsqrtf(vs * (1.0f / 64.0f) + 1e-5f);

    __syncthreads();   // done reading a_s; reuse for output staging
    #pragma unroll
    for (int j = 0; j < 64; j++) {
        a_s[j * 128 + tid] =
            (h[j] - mu) * rstd * __ldg(&gamma[j]) + __ldg(&beta[j]);
    }
    __syncthreads();

    for (int idx = tid; idx < 128 * 16; idx += 128) {
        int node = idx >> 4, k4 = idx & 15;
        int n2 = node0 + node;
        if (n2 < N_NODES) {
            float4 v;
            v.x = a_s[(k4 * 4 + 0) * 128 + node];
            v.y = a_s[(k4 * 4 + 1) * 128 + node];
            v.z = a_s[(k4 * 4 + 2) * 128 + node];
            v.w = a_s[(k4 * 4 + 3) * 128 + node];
            reinterpret_cast<float4*>(out)[n2 * 16 + k4] = v;
        }
    }
}

// ---------------- launch ----------------
extern "C" void kernel_launch(void* const* d_in, const int* in_sizes, int n_in,
                              void* d_out, int out_size) {
    const float* x         = (const float*)d_in[0];
    const float* edge_attr = (const float*)d_in[1];
    const float* W1        = (const float*)d_in[2];
    const float* W2        = (const float*)d_in[3];
    const float* att_l     = (const float*)d_in[4];
    const float* att_r     = (const float*)d_in[5];
    const float* bias      = (const float*)d_in[6];
    const float* ln_gamma  = (const float*)d_in[7];
    const float* ln_beta   = (const float*)d_in[8];
    const int*   src       = (const int*)d_in[9];
    const int*   dst       = (const int*)d_in[10];
    float* out = (float*)d_out;

    k_u<<<1, 96>>>(W1, att_l);
    k_pre<<<(N_NODES * 32 + 255) / 256, 256>>>(x, att_r);
    k_count<<<(N_EDGES + 255) / 256, 256>>>(dst);
    k_scan_a<<<NBLK_SCAN, 256>>>();
    k_scan_c<<<NBLK_SCAN, 256>>>();
    k_edge<<<(N_EDGES + 255) / 256, 256>>>(edge_attr, src, dst);
    k_agg<<<(N_NODES + 7) / 8, 256>>>();
    k_out<<<(N_NODES + 127) / 128, 128>>>(W2, bias, ln_gamma, ln_beta, out);
}